// round 15
// baseline (speedup 1.0000x reference)
#include <cuda_runtime.h>
#include <cuda_bf16.h>
#include <math_constants.h>
#include <cstdint>

#define L     8192
#define D     64
#define BM    128            // query rows per CTA
#define NCH   4
#define CHUNK 2048           // L / NCH
#define BN1   64             // pass1 key-tile width
#define T1    32             // CHUNK / BN1
#define BN2   64             // pass2 key-tile width
#define T2    32             // CHUNK / BN2
#define NT    256

// ---------------- scratch (__device__ globals; no allocation allowed) -------
__device__ float g_l[L];     // row sums of exp(s), atomically accumulated
// 2-limb bf16 versions of Q, K, V (prep kernel fills once)
__device__ __nv_bfloat16 gQh[L * D], gQl[L * D];
__device__ __nv_bfloat16 gKh[L * D], gKl[L * D];
__device__ __nv_bfloat16 gVh[L * D], gVl[L * D];
// 2-limb bf16 of e = exp(QK^T), written by pass1, consumed by pass2
__device__ __nv_bfloat16 gEh[(size_t)L * L];   // 134 MB
__device__ __nv_bfloat16 gEl[(size_t)L * L];   // 134 MB

// ---------------- helpers ---------------------------------------------------
__device__ __forceinline__ uint32_t smem_to_u32(const void* p) {
    uint32_t a;
    asm("{ .reg .u64 t; cvta.to.shared.u64 t, %1; cvt.u32.u64 %0, t; }"
        : "=r"(a) : "l"(p));
    return a;
}
#define CP_ASYNC16(dst, src) \
    asm volatile("cp.async.cg.shared.global [%0], [%1], 16;" \
                 :: "r"(dst), "l"(src) : "memory")
#define CP_COMMIT() asm volatile("cp.async.commit_group;" ::: "memory")
#define CP_WAIT(n)  asm volatile("cp.async.wait_group %0;" :: "n"(n) : "memory")

__device__ __forceinline__ void ldsm_x4(uint32_t* r, uint32_t a) {
    asm volatile("ldmatrix.sync.aligned.m8n8.x4.shared.b16 {%0,%1,%2,%3}, [%4];"
                 : "=r"(r[0]), "=r"(r[1]), "=r"(r[2]), "=r"(r[3]) : "r"(a));
}
__device__ __forceinline__ void ldsm_x4_t(uint32_t* r, uint32_t a) {
    asm volatile("ldmatrix.sync.aligned.m8n8.x4.trans.shared.b16 {%0,%1,%2,%3}, [%4];"
                 : "=r"(r[0]), "=r"(r[1]), "=r"(r[2]), "=r"(r[3]) : "r"(a));
}
__device__ __forceinline__ void mma_bf16(float* c, const uint32_t* a,
                                         uint32_t b0, uint32_t b1) {
    asm volatile("mma.sync.aligned.m16n8k16.row.col.f32.bf16.bf16.f32 "
                 "{%0,%1,%2,%3}, {%4,%5,%6,%7}, {%8,%9}, {%0,%1,%2,%3};"
                 : "+f"(c[0]), "+f"(c[1]), "+f"(c[2]), "+f"(c[3])
                 : "r"(a[0]), "r"(a[1]), "r"(a[2]), "r"(a[3]), "r"(b0), "r"(b1));
}
__device__ __forceinline__ void split2(float x, float y,
                                       __nv_bfloat162& h2, __nv_bfloat162& l2) {
    __nv_bfloat16 hx = __float2bfloat16(x);
    __nv_bfloat16 hy = __float2bfloat16(y);
    h2.x = hx; h2.y = hy;
    l2.x = __float2bfloat16(x - __bfloat162float(hx));
    l2.y = __float2bfloat16(y - __bfloat162float(hy));
}
// SW128 swizzle: 128B rows, 16B chunks; chunk c of row r lives at c^(r&7)
__device__ __forceinline__ uint32_t swo(int r, int c16) {
    return (uint32_t)(r * 128 + ((c16 ^ (r & 7)) << 4));
}

// pass1 smem byte offsets (swizzled 128B rows)
#define SQH 0
#define SQL 16384
#define SK0 32768              // buf b at SK0 + b*16384 (hi +0, lo +8192)
#define P1_SMEM  65536
// pass2 smem byte offsets
#define SE0 0                  // E buf b at b*32768 (hi +0, lo +16384)
#define SV0 65536              // V buf b at SV0 + b*16384 (hi +0, lo +8192)
#define P2_STATS 98304
#define P2_SMEM  (98304 + 512)

// ---------------------------------------------------------------------------
// Prep: split Q, K, V into bf16 hi/lo limb arrays; y==3 zeroes O and g_l
// ---------------------------------------------------------------------------
__global__ void prep_kernel(const float* __restrict__ Q,
                            const float* __restrict__ Km,
                            const float* __restrict__ V,
                            float* __restrict__ O) {
    const int idx = blockIdx.x * 256 + threadIdx.x;    // float2 index
    if (blockIdx.y == 3) {     // zero O (L*D floats) + g_l
        if (idx < L * D / 4)
            *(float4*)&O[idx * 4] = make_float4(0.f, 0.f, 0.f, 0.f);
        if (idx < L / 4)
            *(float4*)&g_l[idx * 4] = make_float4(0.f, 0.f, 0.f, 0.f);
        return;
    }
    const float* src; __nv_bfloat16 *dh, *dl;
    if (blockIdx.y == 0)      { src = Q;  dh = gQh; dl = gQl; }
    else if (blockIdx.y == 1) { src = Km; dh = gKh; dl = gKl; }
    else                      { src = V;  dh = gVh; dl = gVl; }
    const float2 v = *(const float2*)&src[idx * 2];
    __nv_bfloat162 h2, l2; split2(v.x, v.y, h2, l2);
    *(__nv_bfloat162*)&dh[idx * 2] = h2;
    *(__nv_bfloat162*)&dl[idx * 2] = l2;
}

// ---------------------------------------------------------------------------
// Pass 1: e = exp(Q K^T) written as bf16 limbs to gEh/gEl + row sums to g_l
// ---------------------------------------------------------------------------
__global__ __launch_bounds__(NT, 3) void pass1_kernel() {
    extern __shared__ char smem[];
    const uint32_t sb = smem_to_u32(smem);
    const int tid  = threadIdx.x;
    const int lane = tid & 31;
    const int w    = tid >> 5;
    const int wr   = (w & 3) * 32;
    const int wc   = (w >> 2) * 32;
    const int rowblk  = blockIdx.y * BM;
    const int colbase = blockIdx.x * CHUNK;

#pragma unroll
    for (int i = 0; i < 8; i++) {
        const int idx = tid + i * NT;                // 2048 chunks
        const int limb = idx >> 10, rem = idx & 1023;
        const int r = rem >> 3, c = rem & 7;
        const __nv_bfloat16* src =
            (limb ? gQl : gQh) + (size_t)(rowblk + r) * D + c * 8;
        CP_ASYNC16(sb + (limb ? SQL : SQH) + swo(r, c), src);
    }
#pragma unroll
    for (int i = 0; i < 4; i++) {
        const int idx = tid + i * NT;                // 1024 chunks
        const int limb = idx >> 9, rem = idx & 511;
        const int r = rem >> 3, c = rem & 7;
        const __nv_bfloat16* src =
            (limb ? gKl : gKh) + (size_t)(colbase + r) * D + c * 8;
        CP_ASYNC16(sb + SK0 + limb * 8192 + swo(r, c), src);
    }
    CP_COMMIT();

    const int a_row = (lane & 7) + (lane & 8);
    const int a_c   = (lane >> 4) & 1;
    const int b_n   = (lane & 7) + ((lane >> 4) & 1) * 8;
    const int b_c   = (lane >> 3) & 1;
    const int g = lane >> 2, tq = lane & 3;

    float rsum[2][2] = {{0.f, 0.f}, {0.f, 0.f}};

    for (int t = 0; t < T1; t++) {
        CP_WAIT(0);
        __syncthreads();

        if (t + 1 < T1) {
            const int kb1 = colbase + (t + 1) * BN1;
            const uint32_t kd = sb + SK0 + ((t + 1) & 1) * 16384;
#pragma unroll
            for (int i = 0; i < 4; i++) {
                const int idx = tid + i * NT;
                const int limb = idx >> 9, rem = idx & 511;
                const int r = rem >> 3, c = rem & 7;
                const __nv_bfloat16* src =
                    (limb ? gKl : gKh) + (size_t)(kb1 + r) * D + c * 8;
                CP_ASYNC16(kd + limb * 8192 + swo(r, c), src);
            }
            CP_COMMIT();
        }

        const int kb = colbase + t * BN1;
        const uint32_t skh = sb + SK0 + (t & 1) * 16384;
        const uint32_t skl = skh + 8192;

        float acc[2][4][4];
#pragma unroll
        for (int i = 0; i < 2; i++)
#pragma unroll
            for (int j = 0; j < 4; j++)
#pragma unroll
                for (int e = 0; e < 4; e++) acc[i][j][e] = 0.0f;

#pragma unroll
        for (int ks = 0; ks < 4; ks++) {
            uint32_t aH[2][4], aL[2][4];
#pragma unroll
            for (int i = 0; i < 2; i++) {
                const uint32_t ao = swo(wr + 16 * i + a_row, ks * 2 + a_c);
                ldsm_x4(aH[i], sb + SQH + ao);
                ldsm_x4(aL[i], sb + SQL + ao);
            }
#pragma unroll
            for (int jj = 0; jj < 2; jj++) {
                const uint32_t bo = swo(wc + jj * 16 + b_n, ks * 2 + b_c);
                uint32_t bh[4], bl[4];
                ldsm_x4(bh, skh + bo);
                ldsm_x4(bl, skl + bo);
#pragma unroll
                for (int i = 0; i < 2; i++)
#pragma unroll
                    for (int p = 0; p < 2; p++) {
                        float* c = acc[i][2 * jj + p];
                        mma_bf16(c, aH[i], bh[2 * p], bh[2 * p + 1]);
                        mma_bf16(c, aH[i], bl[2 * p], bl[2 * p + 1]);
                        mma_bf16(c, aL[i], bh[2 * p], bh[2 * p + 1]);
                    }
            }
        }

        // epilogue: e = exp(s); write bf16 limbs to gEh/gEl; row sums
#pragma unroll
        for (int i = 0; i < 2; i++) {
            const int ra = rowblk + wr + 16 * i + g;
            const int cb = kb + wc + 2 * tq;
#pragma unroll
            for (int j = 0; j < 4; j++) {
                const float e0 = __expf(acc[i][j][0]);
                const float e1 = __expf(acc[i][j][1]);
                const float e2 = __expf(acc[i][j][2]);
                const float e3 = __expf(acc[i][j][3]);
                __nv_bfloat162 h2, l2;
                split2(e0, e1, h2, l2);
                *(__nv_bfloat162*)&gEh[(size_t)ra * L + cb + 8 * j] = h2;
                *(__nv_bfloat162*)&gEl[(size_t)ra * L + cb + 8 * j] = l2;
                split2(e2, e3, h2, l2);
                *(__nv_bfloat162*)&gEh[(size_t)(ra + 8) * L + cb + 8 * j] = h2;
                *(__nv_bfloat162*)&gEl[(size_t)(ra + 8) * L + cb + 8 * j] = l2;
                rsum[i][0] += e0 + e1;
                rsum[i][1] += e2 + e3;
            }
        }
    }

#pragma unroll
    for (int i = 0; i < 2; i++)
#pragma unroll
        for (int h = 0; h < 2; h++) {
            float s = rsum[i][h];
            s += __shfl_xor_sync(0xffffffffu, s, 1);
            s += __shfl_xor_sync(0xffffffffu, s, 2);
            if (tq == 0)
                atomicAdd(&g_l[rowblk + wr + 16 * i + 8 * h + g], s);
        }
}

// ---------------------------------------------------------------------------
// Pass 2: E limbs arrive MMA-ready via cp.async (no convert on MMA path).
// p = (hi+lo)/l reconstructed from smem limbs -> S (independent of MMA).
// O scaled by 1/l in epilogue (commutes with cross-chunk atomicAdd).
// ---------------------------------------------------------------------------
__global__ __launch_bounds__(NT, 2) void pass2_kernel(float* __restrict__ S,
                                                      float* __restrict__ O) {
    extern __shared__ char smem[];
    const uint32_t sb = smem_to_u32(smem);
    const int tid  = threadIdx.x;
    const int lane = tid & 31;
    const int w    = tid >> 5;
    const int wr   = 16 * w;
    const int rowblk  = blockIdx.y * BM;
    const int colbase = blockIdx.x * CHUNK;

    float* li_s = (float*)(smem + P2_STATS);
    if (tid < 128) li_s[tid] = 1.0f / g_l[rowblk + tid];

    // prologue: E(0) + V(0)
#pragma unroll
    for (int i = 0; i < 8; i++) {
        const int idx = tid + i * NT;                // 2048 E chunks
        const int limb = idx >> 10, rem = idx & 1023;
        const int rr = rem >> 3, cc = rem & 7;
        const __nv_bfloat16* src =
            (limb ? gEl : gEh) + (size_t)(rowblk + rr) * L + colbase + cc * 8;
        CP_ASYNC16(sb + SE0 + limb * 16384 + swo(rr, cc), src);
    }
#pragma unroll
    for (int i = 0; i < 4; i++) {
        const int idx = tid + i * NT;                // 1024 V chunks
        const int limb = idx >> 9, rem = idx & 511;
        const int rr = rem >> 3, cc = rem & 7;
        const __nv_bfloat16* src =
            (limb ? gVl : gVh) + (size_t)(colbase + rr) * D + cc * 8;
        CP_ASYNC16(sb + SV0 + limb * 8192 + swo(rr, cc), src);
    }
    CP_COMMIT();

    float acc[8][4];
#pragma unroll
    for (int j = 0; j < 8; j++)
#pragma unroll
        for (int e = 0; e < 4; e++) acc[j][e] = 0.0f;

    const int a_row = (lane & 7) + (lane & 8);
    const int a_c   = (lane >> 4) & 1;
    const int bt_k  = (lane & 7) + (lane & 8);
    const int bt_c  = (lane >> 4) & 1;

    for (int t = 0; t < T2; t++) {
        const int kb = colbase + t * BN2;

        CP_WAIT(0);          // E(t), V(t) resident
        __syncthreads();     // tile t-1 fully consumed -> bufs (t+1)&1 free
                             // (publishes li_s on t=0)

        if (t + 1 < T2) {    // stage E(t+1)+V(t+1); overlaps everything below
            const int kb1 = colbase + (t + 1) * BN2;
            const uint32_t ed = sb + SE0 + ((t + 1) & 1) * 32768;
            const uint32_t vd = sb + SV0 + ((t + 1) & 1) * 16384;
#pragma unroll
            for (int i = 0; i < 8; i++) {
                const int idx = tid + i * NT;
                const int limb = idx >> 10, rem = idx & 1023;
                const int rr = rem >> 3, cc = rem & 7;
                const __nv_bfloat16* src =
                    (limb ? gEl : gEh) + (size_t)(rowblk + rr) * L + kb1 + cc * 8;
                CP_ASYNC16(ed + limb * 16384 + swo(rr, cc), src);
            }
#pragma unroll
            for (int i = 0; i < 4; i++) {
                const int idx = tid + i * NT;
                const int limb = idx >> 9, rem = idx & 511;
                const int rr = rem >> 3, cc = rem & 7;
                const __nv_bfloat16* src =
                    (limb ? gVl : gVh) + (size_t)(kb1 + rr) * D + cc * 8;
                CP_ASYNC16(vd + limb * 8192 + swo(rr, cc), src);
            }
            CP_COMMIT();
        }

        const uint32_t seh = sb + SE0 + (t & 1) * 32768;
        const uint32_t sel = seh + 16384;
        const uint32_t svh = sb + SV0 + (t & 1) * 16384;
        const uint32_t svl = svh + 8192;

        // ---- MMA: A = E limbs straight from cp.async'd smem ----
#pragma unroll
        for (int ks = 0; ks < 4; ks++) {
            uint32_t aH[4], aL[4];
            const uint32_t ao = swo(wr + a_row, ks * 2 + a_c);
            ldsm_x4(aH, seh + ao);
            ldsm_x4(aL, sel + ao);
#pragma unroll
            for (int jj = 0; jj < 4; jj++) {
                const uint32_t bo = swo(ks * 16 + bt_k, 2 * jj + bt_c);
                uint32_t bh[4], bl[4];
                ldsm_x4_t(bh, svh + bo);
                ldsm_x4_t(bl, svl + bo);
#pragma unroll
                for (int p = 0; p < 2; p++) {
                    float* c = acc[2 * jj + p];
                    mma_bf16(c, aH, bh[2 * p], bh[2 * p + 1]);
                    mma_bf16(c, aH, bl[2 * p], bl[2 * p + 1]);
                    mma_bf16(c, aL, bh[2 * p], bh[2 * p + 1]);
                }
            }
        }

        // ---- independent: p = (hi+lo)*1/l -> S (from same smem limbs) ----
#pragma unroll
        for (int i = 0; i < 8; i++) {
            const int idx = i * NT + tid;
            const int r = idx >> 4, c4 = idx & 15;
            const uint32_t off = swo(r, c4 >> 1) + (c4 & 1) * 8;
            const uint2 hp = *(const uint2*)(smem + seh - sb + (size_t)0 + off);
            const uint2 lp = *(const uint2*)(smem + sel - sb + (size_t)0 + off);
            const float2 h01 = __bfloat1622float2(*(const __nv_bfloat162*)&hp.x);
            const float2 h23 = __bfloat1622float2(*(const __nv_bfloat162*)&hp.y);
            const float2 l01 = __bfloat1622float2(*(const __nv_bfloat162*)&lp.x);
            const float2 l23 = __bfloat1622float2(*(const __nv_bfloat162*)&lp.y);
            const float sc = li_s[r];
            float4 p4;
            p4.x = (h01.x + l01.x) * sc;
            p4.y = (h01.y + l01.y) * sc;
            p4.z = (h23.x + l23.x) * sc;
            p4.w = (h23.y + l23.y) * sc;
            *(float4*)&S[(size_t)(rowblk + r) * L + kb + c4 * 4] = p4;
        }
    }

    // epilogue: scale O rows by 1/l, then atomic-accumulate (O pre-zeroed)
    const int g = lane >> 2, tq = lane & 3;
    const int ra = rowblk + wr + g;
    const float li0 = li_s[wr + g];
    const float li1 = li_s[wr + 8 + g];
#pragma unroll
    for (int j = 0; j < 8; j++) {
        atomicAdd(&O[(size_t)ra * D + 8 * j + 2 * tq],     acc[j][0] * li0);
        atomicAdd(&O[(size_t)ra * D + 8 * j + 2 * tq + 1], acc[j][1] * li0);
        atomicAdd(&O[(size_t)(ra + 8) * D + 8 * j + 2 * tq],     acc[j][2] * li1);
        atomicAdd(&O[(size_t)(ra + 8) * D + 8 * j + 2 * tq + 1], acc[j][3] * li1);
    }
}

extern "C" void kernel_launch(void* const* d_in, const int* in_sizes, int n_in,
                              void* d_out, int out_size) {
    const float* q = (const float*)d_in[0];
    const float* k = (const float*)d_in[1];
    const float* v = (const float*)d_in[2];

    float* out   = (float*)d_out;          // [L, D]
    float* score = out + (size_t)L * D;    // [L, L]

    cudaFuncSetAttribute(pass1_kernel,
                         cudaFuncAttributeMaxDynamicSharedMemorySize, P1_SMEM);
    cudaFuncSetAttribute(pass2_kernel,
                         cudaFuncAttributeMaxDynamicSharedMemorySize, P2_SMEM);

    dim3 pgrid(L * D / (2 * 256), 4);
    prep_kernel<<<pgrid, 256>>>(q, k, v, out);

    dim3 grid(NCH, L / BM);
    pass1_kernel<<<grid, NT, P1_SMEM>>>();
    pass2_kernel<<<grid, NT, P2_SMEM>>>(score, out);
}

// round 16
// speedup vs baseline: 1.2222x; 1.2222x over previous
#include <cuda_runtime.h>
#include <cuda_bf16.h>
#include <math_constants.h>
#include <cstdint>

#define L     8192
#define D     64
#define BM    128            // query rows per CTA
#define NCH   16
#define CHUNK 512            // L / NCH
#define BN1   64             // pass1 key-tile width
#define T1    8              // CHUNK / BN1
#define BN2   64             // pass2 key-tile width
#define T2    8              // CHUNK / BN2
#define NT    256
#define NRB   (L / BM)       // 64 row blocks

// ---------------- scratch (__device__ globals; no allocation allowed) -------
__device__ float g_l[L];     // row sums of exp(s), atomically accumulated
__device__ int   g_cnt[NRB]; // per-rowblock pass1 completion counters
// 2-limb bf16 versions of Q, K, V (prep kernel fills once)
__device__ __nv_bfloat16 gQh[L * D], gQl[L * D];
__device__ __nv_bfloat16 gKh[L * D], gKl[L * D];
__device__ __nv_bfloat16 gVh[L * D], gVl[L * D];

// ---------------- helpers ---------------------------------------------------
__device__ __forceinline__ uint32_t smem_to_u32(const void* p) {
    uint32_t a;
    asm("{ .reg .u64 t; cvta.to.shared.u64 t, %1; cvt.u32.u64 %0, t; }"
        : "=r"(a) : "l"(p));
    return a;
}
#define CP_ASYNC16(dst, src) \
    asm volatile("cp.async.cg.shared.global [%0], [%1], 16;" \
                 :: "r"(dst), "l"(src) : "memory")
#define CP_COMMIT() asm volatile("cp.async.commit_group;" ::: "memory")
#define CP_WAIT(n)  asm volatile("cp.async.wait_group %0;" :: "n"(n) : "memory")

__device__ __forceinline__ void ldsm_x4(uint32_t* r, uint32_t a) {
    asm volatile("ldmatrix.sync.aligned.m8n8.x4.shared.b16 {%0,%1,%2,%3}, [%4];"
                 : "=r"(r[0]), "=r"(r[1]), "=r"(r[2]), "=r"(r[3]) : "r"(a));
}
__device__ __forceinline__ void ldsm_x4_t(uint32_t* r, uint32_t a) {
    asm volatile("ldmatrix.sync.aligned.m8n8.x4.trans.shared.b16 {%0,%1,%2,%3}, [%4];"
                 : "=r"(r[0]), "=r"(r[1]), "=r"(r[2]), "=r"(r[3]) : "r"(a));
}
__device__ __forceinline__ void mma_bf16(float* c, const uint32_t* a,
                                         uint32_t b0, uint32_t b1) {
    asm volatile("mma.sync.aligned.m16n8k16.row.col.f32.bf16.bf16.f32 "
                 "{%0,%1,%2,%3}, {%4,%5,%6,%7}, {%8,%9}, {%0,%1,%2,%3};"
                 : "+f"(c[0]), "+f"(c[1]), "+f"(c[2]), "+f"(c[3])
                 : "r"(a[0]), "r"(a[1]), "r"(a[2]), "r"(a[3]), "r"(b0), "r"(b1));
}
__device__ __forceinline__ void split2(float x, float y,
                                       __nv_bfloat162& h2, __nv_bfloat162& l2) {
    __nv_bfloat16 hx = __float2bfloat16(x);
    __nv_bfloat16 hy = __float2bfloat16(y);
    h2.x = hx; h2.y = hy;
    l2.x = __float2bfloat16(x - __bfloat162float(hx));
    l2.y = __float2bfloat16(y - __bfloat162float(hy));
}
// SW128 swizzle: 128B rows, 16B chunks; chunk c of row r lives at c^(r&7)
__device__ __forceinline__ uint32_t swo(int r, int c16) {
    return (uint32_t)(r * 128 + ((c16 ^ (r & 7)) << 4));
}

// pass1 smem byte offsets (swizzled 128B rows)
#define SQH 0
#define SQL 16384
#define SK0 32768              // buf b at SK0 + b*16384 (hi +0, lo +8192)
#define P1_SMEM  65536
// pass2 smem byte offsets
#define SPH 0
#define SPL 16384
#define SV0 32768              // buf b at SV0 + b*16384 (hi +0, lo +8192)
#define P2_STATS 65536
#define P2_SMEM  (65536 + 512)

// ---------------------------------------------------------------------------
// Prep: split Q, K, V into bf16 hi/lo limb arrays; y==3 zeroes O, g_l, g_cnt
// ---------------------------------------------------------------------------
__global__ void prep_kernel(const float* __restrict__ Q,
                            const float* __restrict__ Km,
                            const float* __restrict__ V,
                            float* __restrict__ O) {
    const int idx = blockIdx.x * 256 + threadIdx.x;    // float2 index
    if (blockIdx.y == 3) {
        if (idx < L * D / 4)
            *(float4*)&O[idx * 4] = make_float4(0.f, 0.f, 0.f, 0.f);
        if (idx < L / 4)
            *(float4*)&g_l[idx * 4] = make_float4(0.f, 0.f, 0.f, 0.f);
        if (idx < NRB) g_cnt[idx] = 0;
        return;
    }
    const float* src; __nv_bfloat16 *dh, *dl;
    if (blockIdx.y == 0)      { src = Q;  dh = gQh; dl = gQl; }
    else if (blockIdx.y == 1) { src = Km; dh = gKh; dl = gKl; }
    else                      { src = V;  dh = gVh; dl = gVl; }
    const float2 v = *(const float2*)&src[idx * 2];
    __nv_bfloat162 h2, l2; split2(v.x, v.y, h2, l2);
    *(__nv_bfloat162*)&dh[idx * 2] = h2;
    *(__nv_bfloat162*)&dl[idx * 2] = l2;
}

// ---------------------------------------------------------------------------
// Pass 1: S = exp(Q K^T) (no max shift) + row sums; signals per-rowblock flag
// ---------------------------------------------------------------------------
__global__ __launch_bounds__(NT, 3) void pass1_kernel(float* __restrict__ S) {
    // allow the dependent pass2 grid to launch (overlap); spin flags gate data
    asm volatile("griddepcontrol.launch_dependents;");

    extern __shared__ char smem[];
    const uint32_t sb = smem_to_u32(smem);
    const int tid  = threadIdx.x;
    const int lane = tid & 31;
    const int w    = tid >> 5;
    const int wr   = (w & 3) * 32;
    const int wc   = (w >> 2) * 32;
    const int rowblk  = blockIdx.y * BM;
    const int colbase = blockIdx.x * CHUNK;

#pragma unroll
    for (int i = 0; i < 8; i++) {
        const int idx = tid + i * NT;                // 2048 chunks
        const int limb = idx >> 10, rem = idx & 1023;
        const int r = rem >> 3, c = rem & 7;
        const __nv_bfloat16* src =
            (limb ? gQl : gQh) + (size_t)(rowblk + r) * D + c * 8;
        CP_ASYNC16(sb + (limb ? SQL : SQH) + swo(r, c), src);
    }
#pragma unroll
    for (int i = 0; i < 4; i++) {
        const int idx = tid + i * NT;                // 1024 chunks
        const int limb = idx >> 9, rem = idx & 511;
        const int r = rem >> 3, c = rem & 7;
        const __nv_bfloat16* src =
            (limb ? gKl : gKh) + (size_t)(colbase + r) * D + c * 8;
        CP_ASYNC16(sb + SK0 + limb * 8192 + swo(r, c), src);
    }
    CP_COMMIT();

    const int a_row = (lane & 7) + (lane & 8);
    const int a_c   = (lane >> 4) & 1;
    const int b_n   = (lane & 7) + ((lane >> 4) & 1) * 8;
    const int b_c   = (lane >> 3) & 1;
    const int g = lane >> 2, tq = lane & 3;

    float rsum[2][2] = {{0.f, 0.f}, {0.f, 0.f}};

    for (int t = 0; t < T1; t++) {
        CP_WAIT(0);
        __syncthreads();

        if (t + 1 < T1) {
            const int kb1 = colbase + (t + 1) * BN1;
            const uint32_t kd = sb + SK0 + ((t + 1) & 1) * 16384;
#pragma unroll
            for (int i = 0; i < 4; i++) {
                const int idx = tid + i * NT;
                const int limb = idx >> 9, rem = idx & 511;
                const int r = rem >> 3, c = rem & 7;
                const __nv_bfloat16* src =
                    (limb ? gKl : gKh) + (size_t)(kb1 + r) * D + c * 8;
                CP_ASYNC16(kd + limb * 8192 + swo(r, c), src);
            }
            CP_COMMIT();
        }

        const int kb = colbase + t * BN1;
        const uint32_t skh = sb + SK0 + (t & 1) * 16384;
        const uint32_t skl = skh + 8192;

        float acc[2][4][4];
#pragma unroll
        for (int i = 0; i < 2; i++)
#pragma unroll
            for (int j = 0; j < 4; j++)
#pragma unroll
                for (int e = 0; e < 4; e++) acc[i][j][e] = 0.0f;

#pragma unroll
        for (int ks = 0; ks < 4; ks++) {
            uint32_t aH[2][4], aL[2][4];
#pragma unroll
            for (int i = 0; i < 2; i++) {
                const uint32_t ao = swo(wr + 16 * i + a_row, ks * 2 + a_c);
                ldsm_x4(aH[i], sb + SQH + ao);
                ldsm_x4(aL[i], sb + SQL + ao);
            }
#pragma unroll
            for (int jj = 0; jj < 2; jj++) {
                const uint32_t bo = swo(wc + jj * 16 + b_n, ks * 2 + b_c);
                uint32_t bh[4], bl[4];
                ldsm_x4(bh, skh + bo);
                ldsm_x4(bl, skl + bo);
#pragma unroll
                for (int i = 0; i < 2; i++)
#pragma unroll
                    for (int p = 0; p < 2; p++) {
                        float* c = acc[i][2 * jj + p];
                        mma_bf16(c, aH[i], bh[2 * p], bh[2 * p + 1]);
                        mma_bf16(c, aH[i], bl[2 * p], bl[2 * p + 1]);
                        mma_bf16(c, aL[i], bh[2 * p], bh[2 * p + 1]);
                    }
            }
        }

#pragma unroll
        for (int i = 0; i < 2; i++) {
            const int ra = rowblk + wr + 16 * i + g;
            const int cb = kb + wc + 2 * tq;
#pragma unroll
            for (int j = 0; j < 4; j++) {
                const float e0 = __expf(acc[i][j][0]);
                const float e1 = __expf(acc[i][j][1]);
                const float e2 = __expf(acc[i][j][2]);
                const float e3 = __expf(acc[i][j][3]);
                *(float2*)&S[(size_t)ra * L + cb + 8 * j] = make_float2(e0, e1);
                *(float2*)&S[(size_t)(ra + 8) * L + cb + 8 * j] = make_float2(e2, e3);
                rsum[i][0] += e0 + e1;
                rsum[i][1] += e2 + e3;
            }
        }
    }

    // row sums -> g_l
#pragma unroll
    for (int i = 0; i < 2; i++)
#pragma unroll
        for (int h = 0; h < 2; h++) {
            float s = rsum[i][h];
            s += __shfl_xor_sync(0xffffffffu, s, 1);
            s += __shfl_xor_sync(0xffffffffu, s, 2);
            if (tq == 0)
                atomicAdd(&g_l[rowblk + wr + 16 * i + 8 * h + g], s);
        }

    // publish: all S stores + g_l adds for this (chunk, rowblock) are done
    __threadfence();
    __syncthreads();
    if (tid == 0) atomicAdd(&g_cnt[blockIdx.y], 1);
}

// ---------------------------------------------------------------------------
// Pass 2: spins until its rowblock's NCH pass1 chunks are complete, then
// normalize S in place and accumulate O (identical body to R13 pass2).
// ---------------------------------------------------------------------------
__global__ __launch_bounds__(NT, 2) void pass2_kernel(float* __restrict__ S,
                                                      float* __restrict__ O) {
    extern __shared__ char smem[];
    const uint32_t sb = smem_to_u32(smem);
    const int tid  = threadIdx.x;
    const int lane = tid & 31;
    const int w    = tid >> 5;
    const int wr   = 16 * w;
    const int rowblk  = blockIdx.y * BM;
    const int colbase = blockIdx.x * CHUNK;

    // gate: wait for all pass1 chunks of this rowblock
    if (tid == 0) {
        int c;
        do {
            asm volatile("ld.acquire.gpu.global.s32 %0, [%1];"
                         : "=r"(c) : "l"(g_cnt + blockIdx.y) : "memory");
            if (c < NCH) __nanosleep(64);
        } while (c < NCH);
    }
    __syncthreads();

    float* li_s = (float*)(smem + P2_STATS);
    if (tid < 128) li_s[tid] = 1.0f / g_l[rowblk + tid];

    // prologue: V tile 0
#pragma unroll
    for (int i = 0; i < 4; i++) {
        const int idx = tid + i * NT;                // 1024 chunks
        const int limb = idx >> 9, rem = idx & 511;
        const int r = rem >> 3, c = rem & 7;
        const __nv_bfloat16* src =
            (limb ? gVl : gVh) + (size_t)(colbase + r) * D + c * 8;
        CP_ASYNC16(sb + SV0 + limb * 8192 + swo(r, c), src);
    }
    CP_COMMIT();

    // S tile 0 into regs (warp-local rows)
    float4 s4[8];
#pragma unroll
    for (int i = 0; i < 8; i++) {
        const int idx = i * 32 + lane;
        const int rl = idx >> 4, c4 = idx & 15;
        s4[i] = *(const float4*)&S[(size_t)(rowblk + wr + rl) * L +
                                   colbase + c4 * 4];
    }

    float acc[8][4];
#pragma unroll
    for (int j = 0; j < 8; j++)
#pragma unroll
        for (int e = 0; e < 4; e++) acc[j][e] = 0.0f;

    const int a_row = (lane & 7) + (lane & 8);
    const int a_c   = (lane >> 4) & 1;
    const int bt_k  = (lane & 7) + (lane & 8);
    const int bt_c  = (lane >> 4) & 1;

    for (int t = 0; t < T2; t++) {
        const int kb = colbase + t * BN2;

        CP_WAIT(0);
        __syncthreads();

        if (t + 1 < T2) {
            const int kb1 = colbase + (t + 1) * BN2;
            const uint32_t vd = sb + SV0 + ((t + 1) & 1) * 16384;
#pragma unroll
            for (int i = 0; i < 4; i++) {
                const int idx = tid + i * NT;
                const int limb = idx >> 9, rem = idx & 511;
                const int r = rem >> 3, c = rem & 7;
                const __nv_bfloat16* src =
                    (limb ? gVl : gVh) + (size_t)(kb1 + r) * D + c * 8;
                CP_ASYNC16(vd + limb * 8192 + swo(r, c), src);
            }
            CP_COMMIT();
        }

#pragma unroll
        for (int i = 0; i < 8; i++) {
            const int idx = i * 32 + lane;
            const int rl = idx >> 4, c4 = idx & 15;
            const int r = wr + rl;
            const float sc = li_s[r];
            float4 p4;
            p4.x = s4[i].x * sc;
            p4.y = s4[i].y * sc;
            p4.z = s4[i].z * sc;
            p4.w = s4[i].w * sc;
            if (t + 1 < T2)
                s4[i] = *(const float4*)&S[(size_t)(rowblk + r) * L +
                                           kb + BN2 + c4 * 4];
            *(float4*)&S[(size_t)(rowblk + r) * L + kb + c4 * 4] = p4;
            const uint32_t off = swo(r, c4 >> 1) + (c4 & 1) * 8;
            __nv_bfloat162 h2a, l2a, h2b, l2b;
            split2(p4.x, p4.y, h2a, l2a);
            split2(p4.z, p4.w, h2b, l2b);
            uint2 hp, lp;
            hp.x = *(uint32_t*)&h2a; hp.y = *(uint32_t*)&h2b;
            lp.x = *(uint32_t*)&l2a; lp.y = *(uint32_t*)&l2b;
            *(uint2*)(smem + SPH + off) = hp;
            *(uint2*)(smem + SPL + off) = lp;
        }
        __syncwarp();

        const uint32_t svh = sb + SV0 + (t & 1) * 16384;
        const uint32_t svl = svh + 8192;
#pragma unroll
        for (int ks = 0; ks < 4; ks++) {
            uint32_t aH[4], aL[4];
            const uint32_t ao = swo(wr + a_row, ks * 2 + a_c);
            ldsm_x4(aH, sb + SPH + ao);
            ldsm_x4(aL, sb + SPL + ao);
#pragma unroll
            for (int jj = 0; jj < 4; jj++) {
                const uint32_t bo = swo(ks * 16 + bt_k, 2 * jj + bt_c);
                uint32_t bh[4], bl[4];
                ldsm_x4_t(bh, svh + bo);
                ldsm_x4_t(bl, svl + bo);
#pragma unroll
                for (int p = 0; p < 2; p++) {
                    float* c = acc[2 * jj + p];
                    mma_bf16(c, aH, bh[2 * p], bh[2 * p + 1]);
                    mma_bf16(c, aH, bl[2 * p], bl[2 * p + 1]);
                    mma_bf16(c, aL, bh[2 * p], bh[2 * p + 1]);
                }
            }
        }
    }

    // epilogue: atomic-accumulate partial O (O pre-zeroed)
    const int g = lane >> 2, tq = lane & 3;
    const int ra = rowblk + wr + g;
#pragma unroll
    for (int j = 0; j < 8; j++) {
        atomicAdd(&O[(size_t)ra * D + 8 * j + 2 * tq],     acc[j][0]);
        atomicAdd(&O[(size_t)ra * D + 8 * j + 2 * tq + 1], acc[j][1]);
        atomicAdd(&O[(size_t)(ra + 8) * D + 8 * j + 2 * tq],     acc[j][2]);
        atomicAdd(&O[(size_t)(ra + 8) * D + 8 * j + 2 * tq + 1], acc[j][3]);
    }
}

extern "C" void kernel_launch(void* const* d_in, const int* in_sizes, int n_in,
                              void* d_out, int out_size) {
    const float* q = (const float*)d_in[0];
    const float* k = (const float*)d_in[1];
    const float* v = (const float*)d_in[2];

    float* out   = (float*)d_out;          // [L, D]
    float* score = out + (size_t)L * D;    // [L, L]

    cudaFuncSetAttribute(pass1_kernel,
                         cudaFuncAttributeMaxDynamicSharedMemorySize, P1_SMEM);
    cudaFuncSetAttribute(pass2_kernel,
                         cudaFuncAttributeMaxDynamicSharedMemorySize, P2_SMEM);

    dim3 pgrid(L * D / (2 * 256), 4);
    prep_kernel<<<pgrid, 256>>>(q, k, v, out);

    dim3 grid(NCH, L / BM);
    pass1_kernel<<<grid, NT, P1_SMEM>>>(score);

    // pass2 with programmatic dependent launch: may begin while pass1 drains;
    // per-rowblock spin flags gate actual data consumption.
    cudaLaunchConfig_t cfg = {};
    cfg.gridDim  = grid;
    cfg.blockDim = dim3(NT, 1, 1);
    cfg.dynamicSmemBytes = P2_SMEM;
    cfg.stream = 0;
    cudaLaunchAttribute attrs[1];
    attrs[0].id = cudaLaunchAttributeProgrammaticStreamSerialization;
    attrs[0].val.programmaticStreamSerializationAllowed = 1;
    cfg.attrs = attrs;
    cfg.numAttrs = 1;
    if (cudaLaunchKernelEx(&cfg, pass2_kernel, score, out) != cudaSuccess) {
        pass2_kernel<<<grid, NT, P2_SMEM>>>(score, out);   // serial fallback
    }
}